// round 14
// baseline (speedup 1.0000x reference)
#include <cuda_runtime.h>
#include <cuda_fp16.h>
#include <cstdint>

#define SEQ    2048
#define NHEADS 16
#define HDIM   64
#define DM     1024
#define BQ     128
#define BK     64
#define NT     (SEQ / BK)

#define TILE_B   9216            // 64 rows * 144 B
#define KS_OFF   0               // 3 stages of K
#define VS_OFF   (3 * TILE_B)    // 3 stages of V
#define BS_OFF   (6 * TILE_B)    // 256 f32 bias
#define SMEM_SZ  (6 * TILE_B + 1024)

// Precomputed relative-bias table: [head][distance], distance = max(q-k, 0)
__device__ float g_bias[NHEADS * SEQ];
// Pre-converted fp16 K and V (same layout as inputs)
__device__ __half K16[(size_t)4 * SEQ * DM];
__device__ __half V16[(size_t)4 * SEQ * DM];

__global__ void build_bias_kernel(const float* __restrict__ rab) {
    int d = blockIdx.x * blockDim.x + threadIdx.x;
    if (d >= SEQ) return;
    int bkt;
    if (d < 16) {
        bkt = d;
    } else {
        float t = logf((float)d * 0.0625f) / logf(8.0f) * 16.0f;
        bkt = 16 + (int)t;
        if (bkt > 31) bkt = 31;
    }
#pragma unroll
    for (int h = 0; h < NHEADS; ++h)
        g_bias[h * SEQ + d] = rab[bkt * NHEADS + h];
}

// pack two floats into half2 (lo in low half)
__device__ __forceinline__ unsigned pack_h2(float hi, float lo) {
    unsigned r;
    asm("cvt.rn.f16x2.f32 %0, %1, %2;" : "=r"(r) : "f"(hi), "f"(lo));
    return r;
}

__global__ void __launch_bounds__(256) convert_kernel(
    const float* __restrict__ K, const float* __restrict__ V) {
    size_t i = (size_t)blockIdx.x * blockDim.x + threadIdx.x;  // group of 8 elems
    const float4* ks = (const float4*)K + i * 2;
    float4 a = ks[0], b = ks[1];
    uint4 u;
    u.x = pack_h2(a.y, a.x); u.y = pack_h2(a.w, a.z);
    u.z = pack_h2(b.y, b.x); u.w = pack_h2(b.w, b.z);
    ((uint4*)K16)[i] = u;
    const float4* vs = (const float4*)V + i * 2;
    a = vs[0]; b = vs[1];
    u.x = pack_h2(a.y, a.x); u.y = pack_h2(a.w, a.z);
    u.z = pack_h2(b.y, b.x); u.w = pack_h2(b.w, b.z);
    ((uint4*)V16)[i] = u;
}

__device__ __forceinline__ uint32_t s2u(const void* p) {
    uint32_t a;
    asm("{ .reg .u64 t; cvta.to.shared.u64 t, %1; cvt.u32.u64 %0, t; }" : "=r"(a) : "l"(p));
    return a;
}

__device__ __forceinline__ void mma16(float c[4], const unsigned a[4],
                                      unsigned b0, unsigned b1) {
    asm volatile(
        "mma.sync.aligned.m16n8k16.row.col.f32.f16.f16.f32 "
        "{%0,%1,%2,%3}, {%4,%5,%6,%7}, {%8,%9}, {%0,%1,%2,%3};\n"
        : "+f"(c[0]), "+f"(c[1]), "+f"(c[2]), "+f"(c[3])
        : "r"(a[0]), "r"(a[1]), "r"(a[2]), "r"(a[3]), "r"(b0), "r"(b1));
}

__device__ __forceinline__ void ldsm4(unsigned& r0, unsigned& r1, unsigned& r2,
                                      unsigned& r3, uint32_t a) {
    asm volatile("ldmatrix.sync.aligned.m8n8.x4.shared.b16 {%0,%1,%2,%3}, [%4];"
                 : "=r"(r0), "=r"(r1), "=r"(r2), "=r"(r3) : "r"(a));
}
__device__ __forceinline__ void ldsm4t(unsigned& r0, unsigned& r1, unsigned& r2,
                                       unsigned& r3, uint32_t a) {
    asm volatile("ldmatrix.sync.aligned.m8n8.x4.trans.shared.b16 {%0,%1,%2,%3}, [%4];"
                 : "=r"(r0), "=r"(r1), "=r"(r2), "=r"(r3) : "r"(a));
}

// silu(x) = x * (0.5*tanh(0.5x) + 0.5)   (1 MUFU)
__device__ __forceinline__ float silu(float s) {
    float th;
    asm("tanh.approx.f32 %0, %1;" : "=f"(th) : "f"(0.5f * s));
    return s * fmaf(0.5f, th, 0.5f);
}

__device__ __forceinline__ void cp16(uint32_t saddr, const void* gptr) {
    asm volatile("cp.async.cg.shared.global [%0], [%1], 16;"
                 :: "r"(saddr), "l"(gptr) : "memory");
}

// Issue async fp16 tile loads (K and V, 64x64 halves each) into stage s.
__device__ __forceinline__ void issue_loads(uint32_t ksad, uint32_t vsad,
                                            const __half* kg, const __half* vg,
                                            int k0, int tid) {
    const __half* kp = kg + (size_t)k0 * DM;
    const __half* vp = vg + (size_t)k0 * DM;
#pragma unroll
    for (int i = 0; i < 4; ++i) {
        int item = tid + 128 * i;          // 0..511
        int r = item >> 3, c = item & 7;
        uint32_t soff = (uint32_t)(r * 144 + c * 16);
        cp16(ksad + soff, kp + (size_t)r * DM + c * 8);
        cp16(vsad + soff, vp + (size_t)r * DM + c * 8);
    }
}

// One 64-k tile. GEN: per-element bias lookup; else constant cb.
template <bool GEN>
__device__ __forceinline__ void tile_compute(
    uint32_t kadr, uint32_t vadr, const float* __restrict__ Bs, float cb,
    int k0, int qrow0, int g, int t,
    const unsigned (&qa)[2][4][4], float (&oacc)[2][8][4])
{
#pragma unroll
    for (int ncp = 0; ncp < 4; ++ncp) {   // 16 k-positions per iteration
        float sacc[2][2][4];
#pragma unroll
        for (int m = 0; m < 2; ++m)
#pragma unroll
            for (int no = 0; no < 2; ++no)
#pragma unroll
                for (int j = 0; j < 4; ++j) sacc[m][no][j] = 0.0f;

        const uint32_t ka = kadr + ncp * 2304;   // 16 rows * 144B
#pragma unroll
        for (int c = 0; c < 4; ++c) {
            unsigned b0, b1, b2, b3;
            ldsm4(b0, b1, b2, b3, ka + c * 32);
            mma16(sacc[0][0], qa[0][c], b0, b1);
            mma16(sacc[1][0], qa[1][c], b0, b1);
            mma16(sacc[0][1], qa[0][c], b2, b3);
            mma16(sacc[1][1], qa[1][c], b2, b3);
        }

        unsigned af[2][4];
#pragma unroll
        for (int m = 0; m < 2; ++m) {
#pragma unroll
            for (int no = 0; no < 2; ++no) {
                float s0 = sacc[m][no][0], s1 = sacc[m][no][1];
                float s2 = sacc[m][no][2], s3 = sacc[m][no][3];
                if (GEN) {
                    const int col0 = k0 + (ncp * 2 + no) * 8 + 2 * t;
                    const int r0 = qrow0 + m * 16 + g;
                    int d00 = r0 - col0;     if (d00 < 0) d00 = 0;
                    int d01 = r0 - col0 - 1; if (d01 < 0) d01 = 0;
                    int d10 = r0 + 8 - col0; if (d10 < 0) d10 = 0;
                    int d11 = r0 + 7 - col0; if (d11 < 0) d11 = 0;
                    s0 += Bs[d00]; s1 += Bs[d01]; s2 += Bs[d10]; s3 += Bs[d11];
                } else {
                    s0 += cb; s1 += cb; s2 += cb; s3 += cb;
                }
                af[m][no * 2]     = pack_h2(silu(s1), silu(s0));  // rows g
                af[m][no * 2 + 1] = pack_h2(silu(s3), silu(s2));  // rows g+8
            }
        }

        const uint32_t va = vadr + ncp * 2304;
#pragma unroll
        for (int c = 0; c < 4; ++c) {
            unsigned v0, v1, v2, v3;
            ldsm4t(v0, v1, v2, v3, va + c * 32);
            mma16(oacc[0][2 * c],     af[0], v0, v2);
            mma16(oacc[1][2 * c],     af[1], v0, v2);
            mma16(oacc[0][2 * c + 1], af[0], v1, v3);
            mma16(oacc[1][2 * c + 1], af[1], v1, v3);
        }
    }
}

__global__ void __launch_bounds__(128, 3) paa_kernel(
    const float* __restrict__ Q, float* __restrict__ Out)
{
    extern __shared__ char sm[];
    const uint32_t smb = s2u(sm);
    float* Bs = (float*)(sm + BS_OFF);

    const int qt   = blockIdx.x;
    const int h    = blockIdx.y;
    const int b    = blockIdx.z;
    const int tid  = threadIdx.x;
    const int warp = tid >> 5;
    const int lane = tid & 31;
    const int g    = lane >> 2;
    const int t    = lane & 3;

    const size_t headoff = (size_t)b * SEQ * DM + (size_t)h * HDIM;
    const float*  qp = Q + headoff;
    const __half* kg = K16 + headoff;
    const __half* vg = V16 + headoff;

    // bias distances 0..255 cover all non-saturated tiles
    if (tid < 64)
        *(float4*)(Bs + tid * 4) = *(const float4*)(g_bias + h * SEQ + tid * 4);

    // prologue: issue stage-0 and stage-1 loads
    issue_loads(smb + KS_OFF, smb + VS_OFF, kg, vg, 0, tid);
    asm volatile("cp.async.commit_group;" ::: "memory");
    issue_loads(smb + KS_OFF + TILE_B, smb + VS_OFF + TILE_B, kg, vg, BK, tid);
    asm volatile("cp.async.commit_group;" ::: "memory");

    const int qrow0 = qt * BQ + warp * 32;

    // Q fragments (fp16 k16 A layout), register-resident.
    unsigned qa[2][4][4];
#pragma unroll
    for (int m = 0; m < 2; ++m) {
        const int r = qrow0 + m * 16;
#pragma unroll
        for (int dc = 0; dc < 4; ++dc) {
            int c0 = dc * 16 + 2 * t;
            float2 aa = *(const float2*)(qp + (size_t)(r + g)     * DM + c0);
            float2 ab = *(const float2*)(qp + (size_t)(r + g + 8) * DM + c0);
            float2 ac = *(const float2*)(qp + (size_t)(r + g)     * DM + c0 + 8);
            float2 ad = *(const float2*)(qp + (size_t)(r + g + 8) * DM + c0 + 8);
            qa[m][dc][0] = pack_h2(aa.y, aa.x);
            qa[m][dc][1] = pack_h2(ab.y, ab.x);
            qa[m][dc][2] = pack_h2(ac.y, ac.x);
            qa[m][dc][3] = pack_h2(ad.y, ad.x);
        }
    }

    float oacc[2][8][4];
#pragma unroll
    for (int m = 0; m < 2; ++m)
#pragma unroll
        for (int i = 0; i < 8; ++i)
#pragma unroll
            for (int j = 0; j < 4; ++j) oacc[m][i][j] = 0.0f;

    // ldmatrix base lane offsets (loop-invariant)
    const int mi = lane >> 3, li = lane & 7;
    const uint32_t off_l = (uint32_t)(((mi >> 1) * 8 + li) * 144 + (mi & 1) * 16);

    const float cb0_g  = g_bias[h * SEQ];         // distance-0 bucket
    const float cb31_g = g_bias[h * SEQ + 120];   // saturated bucket 31

    int s = 0;
    for (int kt = 0; kt < NT; ++kt) {
        const int k0 = kt * BK;
        // Stage s's loads (group kt) done once <=1 newer group outstanding.
        asm volatile("cp.async.wait_group 1;" ::: "memory");
        __syncthreads();   // all warps: stage s visible AND done reading stage (s+2)%3

        {   // refill stage (s+2)%3 with tile kt+2 (empty commit keeps group count exact)
            int sn = s + 2; if (sn >= 3) sn -= 3;
            if (kt + 2 < NT)
                issue_loads(smb + KS_OFF + sn * TILE_B, smb + VS_OFF + sn * TILE_B,
                            kg, vg, k0 + 2 * BK, tid);
            asm volatile("cp.async.commit_group;" ::: "memory");
        }

        const uint32_t kadr = smb + KS_OFF + s * TILE_B + off_l;
        const uint32_t vadr = smb + VS_OFF + s * TILE_B + off_l;

        const int dlo = qrow0 - k0 - 63;       // min distance in this warp-tile
        const int dhi = qrow0 + 31 - k0;       // max distance
        if (dlo >= 120) {
            tile_compute<false>(kadr, vadr, Bs, cb31_g, k0, qrow0, g, t, qa, oacc);
        } else if (dhi <= 0) {
            tile_compute<false>(kadr, vadr, Bs, cb0_g, k0, qrow0, g, t, qa, oacc);
        } else {
            tile_compute<true>(kadr, vadr, Bs, 0.0f, k0, qrow0, g, t, qa, oacc);
        }
        ++s; if (s >= 3) s -= 3;
    }

    // ---- epilogue ----
#pragma unroll
    for (int m = 0; m < 2; ++m) {
        float* op = Out + headoff + (size_t)(qrow0 + m * 16) * DM;
#pragma unroll
        for (int oc = 0; oc < 8; ++oc) {
            int c = oc * 8 + 2 * t;
            *(float2*)(op + (size_t)g * DM + c)       = make_float2(oacc[m][oc][0], oacc[m][oc][1]);
            *(float2*)(op + (size_t)(g + 8) * DM + c) = make_float2(oacc[m][oc][2], oacc[m][oc][3]);
        }
    }
}

extern "C" void kernel_launch(void* const* d_in, const int* in_sizes, int n_in,
                              void* d_out, int out_size) {
    // metadata order: v, k, q, rab_weight
    const float* v   = (const float*)d_in[0];
    const float* k   = (const float*)d_in[1];
    const float* q   = (const float*)d_in[2];
    const float* rab = (const float*)d_in[3];
    float* out = (float*)d_out;

    build_bias_kernel<<<SEQ / 256, 256>>>(rab);
    convert_kernel<<<(4 * SEQ * DM / 8) / 256, 256>>>(k, v);

    static int configured = 0;
    if (!configured) {
        cudaFuncSetAttribute(paa_kernel,
                             cudaFuncAttributeMaxDynamicSharedMemorySize, SMEM_SZ);
        configured = 1;
    }
    dim3 grid(SEQ / BQ, NHEADS, 4);
    paa_kernel<<<grid, 128, SMEM_SZ>>>(q, out);
}

// round 15
// speedup vs baseline: 1.5174x; 1.5174x over previous
#include <cuda_runtime.h>
#include <cuda_fp16.h>
#include <cstdint>

#define SEQ    2048
#define NHEADS 16
#define HDIM   64
#define DM     1024
#define BQ     128
#define BK     64
#define NT     (SEQ / BK)
#define STRW   36   // words per smem row: 64 halves (32 w) + 4 pad words = 144B

// Precomputed relative-bias table: [head][distance], distance = max(q-k, 0)
__device__ float g_bias[NHEADS * SEQ];
// Pre-converted fp16 K and V (same layout as inputs)
__device__ __half K16[(size_t)4 * SEQ * DM];
__device__ __half V16[(size_t)4 * SEQ * DM];

// pack two floats into half2 (lo in low half)
__device__ __forceinline__ unsigned pack_h2(float hi, float lo) {
    unsigned r;
    asm("cvt.rn.f16x2.f32 %0, %1, %2;" : "=r"(r) : "f"(hi), "f"(lo));
    return r;
}

// Setup: fp16 conversion of K/V everywhere; blocks 0..7 also build the bias table.
__global__ void __launch_bounds__(256) setup_kernel(
    const float* __restrict__ K, const float* __restrict__ V,
    const float* __restrict__ rab) {
    size_t i = (size_t)blockIdx.x * blockDim.x + threadIdx.x;  // group of 8 elems
    const float4* ks = (const float4*)K + i * 2;
    float4 a = ks[0], b = ks[1];
    uint4 u;
    u.x = pack_h2(a.y, a.x); u.y = pack_h2(a.w, a.z);
    u.z = pack_h2(b.y, b.x); u.w = pack_h2(b.w, b.z);
    ((uint4*)K16)[i] = u;
    const float4* vs = (const float4*)V + i * 2;
    a = vs[0]; b = vs[1];
    u.x = pack_h2(a.y, a.x); u.y = pack_h2(a.w, a.z);
    u.z = pack_h2(b.y, b.x); u.w = pack_h2(b.w, b.z);
    ((uint4*)V16)[i] = u;

    if (blockIdx.x < 8) {
        int d = blockIdx.x * 256 + threadIdx.x;   // 0..2047
        int bkt;
        if (d < 16) {
            bkt = d;
        } else {
            float t = logf((float)d * 0.0625f) / logf(8.0f) * 16.0f;
            bkt = 16 + (int)t;
            if (bkt > 31) bkt = 31;
        }
#pragma unroll
        for (int h = 0; h < NHEADS; ++h)
            g_bias[h * SEQ + d] = rab[bkt * NHEADS + h];
    }
}

__device__ __forceinline__ uint32_t s2u(const void* p) {
    uint32_t a;
    asm("{ .reg .u64 t; cvta.to.shared.u64 t, %1; cvt.u32.u64 %0, t; }" : "=r"(a) : "l"(p));
    return a;
}

__device__ __forceinline__ void mma16(float c[4], const unsigned a[4],
                                      unsigned b0, unsigned b1) {
    asm volatile(
        "mma.sync.aligned.m16n8k16.row.col.f32.f16.f16.f32 "
        "{%0,%1,%2,%3}, {%4,%5,%6,%7}, {%8,%9}, {%0,%1,%2,%3};\n"
        : "+f"(c[0]), "+f"(c[1]), "+f"(c[2]), "+f"(c[3])
        : "r"(a[0]), "r"(a[1]), "r"(a[2]), "r"(a[3]), "r"(b0), "r"(b1));
}

__device__ __forceinline__ void ldsm4(unsigned& r0, unsigned& r1, unsigned& r2,
                                      unsigned& r3, uint32_t a) {
    asm volatile("ldmatrix.sync.aligned.m8n8.x4.shared.b16 {%0,%1,%2,%3}, [%4];"
                 : "=r"(r0), "=r"(r1), "=r"(r2), "=r"(r3) : "r"(a));
}
__device__ __forceinline__ void ldsm4t(unsigned& r0, unsigned& r1, unsigned& r2,
                                       unsigned& r3, uint32_t a) {
    asm volatile("ldmatrix.sync.aligned.m8n8.x4.trans.shared.b16 {%0,%1,%2,%3}, [%4];"
                 : "=r"(r0), "=r"(r1), "=r"(r2), "=r"(r3) : "r"(a));
}

// silu(x) = x * (0.5*tanh(0.5x) + 0.5)   (1 MUFU)
__device__ __forceinline__ float silu(float s) {
    float th;
    asm("tanh.approx.f32 %0, %1;" : "=f"(th) : "f"(0.5f * s));
    return s * fmaf(0.5f, th, 0.5f);
}

__device__ __forceinline__ void cp16(uint32_t saddr, const void* gptr) {
    asm volatile("cp.async.cg.shared.global [%0], [%1], 16;"
                 :: "r"(saddr), "l"(gptr) : "memory");
}

// Issue async fp16 tile loads (K and V, 64x64 halves each) into stage buffers.
__device__ __forceinline__ void issue_loads(uint32_t ksad, uint32_t vsad,
                                            const __half* kg, const __half* vg,
                                            int k0, int tid) {
    const __half* kp = kg + (size_t)k0 * DM;
    const __half* vp = vg + (size_t)k0 * DM;
#pragma unroll
    for (int i = 0; i < 4; ++i) {
        int item = tid + 128 * i;          // 0..511
        int r = item >> 3, c = item & 7;
        uint32_t soff = (uint32_t)(r * 144 + c * 16);
        cp16(ksad + soff, kp + (size_t)r * DM + c * 8);
        cp16(vsad + soff, vp + (size_t)r * DM + c * 8);
    }
}

// One 64-k tile. GEN: per-element bias lookup; else constant cb.
template <bool GEN>
__device__ __forceinline__ void tile_compute(
    uint32_t kadr, uint32_t vadr, const float* __restrict__ Bs, float cb,
    int k0, int qrow0, int g, int t,
    const unsigned (&qa)[2][4][4], float (&oacc)[2][8][4])
{
#pragma unroll
    for (int ncp = 0; ncp < 4; ++ncp) {   // 16 k-positions per iteration
        float sacc[2][2][4];
#pragma unroll
        for (int m = 0; m < 2; ++m)
#pragma unroll
            for (int no = 0; no < 2; ++no)
#pragma unroll
                for (int j = 0; j < 4; ++j) sacc[m][no][j] = 0.0f;

        const uint32_t ka = kadr + ncp * 2304;   // 16 rows * 144B
#pragma unroll
        for (int c = 0; c < 4; ++c) {
            unsigned b0, b1, b2, b3;
            ldsm4(b0, b1, b2, b3, ka + c * 32);
            mma16(sacc[0][0], qa[0][c], b0, b1);
            mma16(sacc[1][0], qa[1][c], b0, b1);
            mma16(sacc[0][1], qa[0][c], b2, b3);
            mma16(sacc[1][1], qa[1][c], b2, b3);
        }

        unsigned af[2][4];
#pragma unroll
        for (int m = 0; m < 2; ++m) {
#pragma unroll
            for (int no = 0; no < 2; ++no) {
                float s0 = sacc[m][no][0], s1 = sacc[m][no][1];
                float s2 = sacc[m][no][2], s3 = sacc[m][no][3];
                if (GEN) {
                    const int col0 = k0 + (ncp * 2 + no) * 8 + 2 * t;
                    const int r0 = qrow0 + m * 16 + g;
                    int d00 = r0 - col0;     if (d00 < 0) d00 = 0;
                    int d01 = r0 - col0 - 1; if (d01 < 0) d01 = 0;
                    int d10 = r0 + 8 - col0; if (d10 < 0) d10 = 0;
                    int d11 = r0 + 7 - col0; if (d11 < 0) d11 = 0;
                    s0 += Bs[d00]; s1 += Bs[d01]; s2 += Bs[d10]; s3 += Bs[d11];
                } else {
                    s0 += cb; s1 += cb; s2 += cb; s3 += cb;
                }
                af[m][no * 2]     = pack_h2(silu(s1), silu(s0));  // rows g
                af[m][no * 2 + 1] = pack_h2(silu(s3), silu(s2));  // rows g+8
            }
        }

        const uint32_t va = vadr + ncp * 2304;
#pragma unroll
        for (int c = 0; c < 4; ++c) {
            unsigned v0, v1, v2, v3;
            ldsm4t(v0, v1, v2, v3, va + c * 32);
            mma16(oacc[0][2 * c],     af[0], v0, v2);
            mma16(oacc[1][2 * c],     af[1], v0, v2);
            mma16(oacc[0][2 * c + 1], af[0], v1, v3);
            mma16(oacc[1][2 * c + 1], af[1], v1, v3);
        }
    }
}

__global__ void __launch_bounds__(128, 3) paa_kernel(
    const float* __restrict__ Q, float* __restrict__ Out)
{
    // Double-buffered natural row-major fp16 tiles; rows 144B.
    __shared__ __half Ks[2][BK * STRW * 2];
    __shared__ __half Vs[2][BK * STRW * 2];
    __shared__ float  Bs[256];

    const int qt   = blockIdx.x;
    const int h    = blockIdx.y;
    const int b    = blockIdx.z;
    const int tid  = threadIdx.x;
    const int warp = tid >> 5;
    const int lane = tid & 31;
    const int g    = lane >> 2;
    const int t    = lane & 3;

    const size_t headoff = (size_t)b * SEQ * DM + (size_t)h * HDIM;
    const float*  qp = Q + headoff;
    const __half* kg = K16 + headoff;
    const __half* vg = V16 + headoff;

    // bias distances 0..255 cover all non-saturated tiles
    if (tid < 64)
        *(float4*)(Bs + tid * 4) = *(const float4*)(g_bias + h * SEQ + tid * 4);

    // stage smem base addresses
    const uint32_t ksad0 = s2u(Ks[0]), ksad1 = s2u(Ks[1]);
    const uint32_t vsad0 = s2u(Vs[0]), vsad1 = s2u(Vs[1]);

    // prologue: issue stage-0 loads immediately
    issue_loads(ksad0, vsad0, kg, vg, 0, tid);
    asm volatile("cp.async.commit_group;" ::: "memory");

    const int qrow0 = qt * BQ + warp * 32;

    // Q fragments (fp16 k16 A layout), register-resident.
    unsigned qa[2][4][4];
#pragma unroll
    for (int m = 0; m < 2; ++m) {
        const int r = qrow0 + m * 16;
#pragma unroll
        for (int dc = 0; dc < 4; ++dc) {
            int c0 = dc * 16 + 2 * t;
            float2 aa = *(const float2*)(qp + (size_t)(r + g)     * DM + c0);
            float2 ab = *(const float2*)(qp + (size_t)(r + g + 8) * DM + c0);
            float2 ac = *(const float2*)(qp + (size_t)(r + g)     * DM + c0 + 8);
            float2 ad = *(const float2*)(qp + (size_t)(r + g + 8) * DM + c0 + 8);
            qa[m][dc][0] = pack_h2(aa.y, aa.x);
            qa[m][dc][1] = pack_h2(ab.y, ab.x);
            qa[m][dc][2] = pack_h2(ac.y, ac.x);
            qa[m][dc][3] = pack_h2(ad.y, ad.x);
        }
    }

    float oacc[2][8][4];
#pragma unroll
    for (int m = 0; m < 2; ++m)
#pragma unroll
        for (int i = 0; i < 8; ++i)
#pragma unroll
            for (int j = 0; j < 4; ++j) oacc[m][i][j] = 0.0f;

    // ldmatrix base lane offsets (loop-invariant)
    const int mi = lane >> 3, li = lane & 7;
    const uint32_t off_l = (uint32_t)(((mi >> 1) * 8 + li) * 144 + (mi & 1) * 16);

    const float cb0_g  = g_bias[h * SEQ];         // distance-0 bucket
    const float cb31_g = g_bias[h * SEQ + 120];   // saturated bucket 31

    for (int kt = 0; kt < NT; ++kt) {
        const int s = kt & 1;
        const int k0 = kt * BK;
        asm volatile("cp.async.wait_group 0;" ::: "memory");
        __syncthreads();   // stage s visible to all; all warps past reading stage s^1

        if (kt + 1 < NT) {
            issue_loads(s ? ksad0 : ksad1, s ? vsad0 : vsad1, kg, vg,
                        k0 + BK, tid);
            asm volatile("cp.async.commit_group;" ::: "memory");
        }

        const uint32_t kadr = (s ? ksad1 : ksad0) + off_l;
        const uint32_t vadr = (s ? vsad1 : vsad0) + off_l;

        const int dlo = qrow0 - k0 - 63;       // min distance in this warp-tile
        const int dhi = qrow0 + 31 - k0;       // max distance
        if (dlo >= 120) {
            tile_compute<false>(kadr, vadr, Bs, cb31_g, k0, qrow0, g, t, qa, oacc);
        } else if (dhi <= 0) {
            tile_compute<false>(kadr, vadr, Bs, cb0_g, k0, qrow0, g, t, qa, oacc);
        } else {
            tile_compute<true>(kadr, vadr, Bs, 0.0f, k0, qrow0, g, t, qa, oacc);
        }
        // NOTE: no bottom barrier. Next iteration's top __syncthreads (after its
        // wait_group) orders all warps past this tile's reads before stage s is
        // refilled in iteration kt+1.
    }

    // ---- epilogue ----
#pragma unroll
    for (int m = 0; m < 2; ++m) {
        float* op = Out + headoff + (size_t)(qrow0 + m * 16) * DM;
#pragma unroll
        for (int oc = 0; oc < 8; ++oc) {
            int c = oc * 8 + 2 * t;
            *(float2*)(op + (size_t)g * DM + c)       = make_float2(oacc[m][oc][0], oacc[m][oc][1]);
            *(float2*)(op + (size_t)(g + 8) * DM + c) = make_float2(oacc[m][oc][2], oacc[m][oc][3]);
        }
    }
}

extern "C" void kernel_launch(void* const* d_in, const int* in_sizes, int n_in,
                              void* d_out, int out_size) {
    // metadata order: v, k, q, rab_weight
    const float* v   = (const float*)d_in[0];
    const float* k   = (const float*)d_in[1];
    const float* q   = (const float*)d_in[2];
    const float* rab = (const float*)d_in[3];
    float* out = (float*)d_out;

    setup_kernel<<<(4 * SEQ * DM / 8) / 256, 256>>>(k, v, rab);

    dim3 grid(SEQ / BQ, NHEADS, 4);
    paa_kernel<<<grid, 128>>>(q, out);
}